// round 3
// baseline (speedup 1.0000x reference)
#include <cuda_runtime.h>
#include <math.h>
#include <stdint.h>

// ---------------------------------------------------------------------------
// FedTGPClientLoss:
//   ce    = mean_b [ logsumexp(logits[b,:]) - logits[b, label_b] ]   (0 if !finite)
//   proto = mean_b mean_d (features[b,d] - protos[label_b, d])^2
//   total = ce + proto                                               (ce if !finite)
// Output: [total, ce, proto]  (3 × f32)
// ---------------------------------------------------------------------------

#define MAXB 32768
__device__ float g_ce[MAXB];
__device__ float g_mse[MAXB];
__device__ int   g_lbl64;   // 1 if labels buffer is int64, 0 if int32

// Detect label dtype: view buffer as int32. For int64 labels < 1000, every
// odd-index 32-bit word (the high half) is 0. For int32 labels, odd indices
// are uniform [0,1000) -> all-zero has probability ~0. Scanning only the
// first B int32 words is in-bounds under BOTH interpretations.
__global__ void detect_labels_kernel(const int* __restrict__ l32, int B) {
    __shared__ int any_nz;
    if (threadIdx.x == 0) any_nz = 0;
    __syncthreads();
    int local = 0;
    for (int i = 1 + 2 * threadIdx.x; i < B; i += 2 * blockDim.x)
        local |= l32[i];
    if (local) atomicOr(&any_nz, 1);
    __syncthreads();
    if (threadIdx.x == 0) g_lbl64 = (any_nz == 0) ? 1 : 0;
}

// One block per row. 256 threads. Single pass over logits with online
// logsumexp (float4 vectorized), fused with the per-row proto MSE.
__global__ __launch_bounds__(256) void row_kernel(
    const float* __restrict__ logits,
    const void*  __restrict__ labels,
    const float* __restrict__ features,
    const float* __restrict__ protos,
    int C, int D)
{
    const int row = blockIdx.x;
    const int tid = threadIdx.x;

    int label;
    if (g_lbl64) label = (int)(((const long long*)labels)[row]);
    else         label = ((const int*)labels)[row];

    // ---- online logsumexp over this row's C logits ----
    const float4* lrow = (const float4*)(logits + (size_t)row * C);
    const int C4 = C >> 2;
    const int lbl4 = label >> 2, lblc = label & 3;

    __shared__ float s_lbl_logit;
    float m = -INFINITY, s = 0.0f;

    for (int i = tid; i < C4; i += blockDim.x) {
        float4 v = lrow[i];
        if (i == lbl4) {
            s_lbl_logit = (lblc == 0) ? v.x : (lblc == 1) ? v.y
                         : (lblc == 2) ? v.z : v.w;
        }
        float lm = fmaxf(fmaxf(v.x, v.y), fmaxf(v.z, v.w));
        float nm = fmaxf(m, lm);
        s = s * __expf(m - nm)
          + __expf(v.x - nm) + __expf(v.y - nm)
          + __expf(v.z - nm) + __expf(v.w - nm);
        m = nm;
    }

    // ---- per-row proto MSE ----
    const float4* frow = (const float4*)(features + (size_t)row   * D);
    const float4* prow = (const float4*)(protos   + (size_t)label * D);
    const int D4 = D >> 2;
    float sq = 0.0f;
    for (int i = tid; i < D4; i += blockDim.x) {
        float4 f = frow[i];
        float4 p = prow[i];
        float dx = f.x - p.x, dy = f.y - p.y, dz = f.z - p.z, dw = f.w - p.w;
        sq = fmaf(dx, dx, fmaf(dy, dy, fmaf(dz, dz, fmaf(dw, dw, sq))));
    }

    // ---- block reduction: (m,s) logsumexp-merge + sq sum ----
    __shared__ float sm_m[256], sm_s[256], sm_q[256];
    sm_m[tid] = m; sm_s[tid] = s; sm_q[tid] = sq;
    __syncthreads();
    for (int off = blockDim.x >> 1; off > 0; off >>= 1) {
        if (tid < off) {
            float m1 = sm_m[tid],       s1 = sm_s[tid];
            float m2 = sm_m[tid + off], s2 = sm_s[tid + off];
            float nm = fmaxf(m1, m2);
            float ns = 0.0f;
            if (s1 > 0.0f) ns += s1 * __expf(m1 - nm);
            if (s2 > 0.0f) ns += s2 * __expf(m2 - nm);
            sm_m[tid] = nm; sm_s[tid] = ns;
            sm_q[tid] += sm_q[tid + off];
        }
        __syncthreads();
    }

    if (tid == 0) {
        float lse = sm_m[0] + __logf(sm_s[0]);
        g_ce[row]  = lse - s_lbl_logit;
        g_mse[row] = sm_q[0] / (float)D;
    }
}

// Single-block final reduction in double precision; writes the 3 outputs.
__global__ __launch_bounds__(1024) void final_kernel(float* __restrict__ out, int B) {
    __shared__ double sm[1024];
    const int tid = threadIdx.x;
    double ce = 0.0, ms = 0.0;
    for (int i = tid; i < B; i += blockDim.x) {
        ce += (double)g_ce[i];
        ms += (double)g_mse[i];
    }
    sm[tid] = ce; __syncthreads();
    for (int off = blockDim.x >> 1; off > 0; off >>= 1) {
        if (tid < off) sm[tid] += sm[tid + off];
        __syncthreads();
    }
    double ce_sum = sm[0];
    __syncthreads();
    sm[tid] = ms; __syncthreads();
    for (int off = blockDim.x >> 1; off > 0; off >>= 1) {
        if (tid < off) sm[tid] += sm[tid + off];
        __syncthreads();
    }
    if (tid == 0) {
        float ce_loss = (float)(ce_sum / (double)B);
        if (!isfinite(ce_loss)) ce_loss = 0.0f;
        float proto_loss = (float)(sm[0] / (double)B);
        float total = ce_loss + proto_loss;
        if (!isfinite(total)) total = ce_loss;
        out[0] = total;
        out[1] = ce_loss;
        out[2] = proto_loss;
    }
}

extern "C" void kernel_launch(void* const* d_in, const int* in_sizes, int n_in,
                              void* d_out, int out_size) {
    const float* logits   = (const float*)d_in[0];
    const void*  labels   = d_in[1];
    const float* features = (const float*)d_in[2];
    const float* protos   = (const float*)d_in[3];
    float* out = (float*)d_out;

    const int B = in_sizes[1];                 // 16384
    const int C = in_sizes[0] / B;             // 1000
    const int D = in_sizes[2] / B;             // 512

    detect_labels_kernel<<<1, 256>>>((const int*)labels, B);
    row_kernel<<<B, 256>>>(logits, labels, features, protos, C, D);
    final_kernel<<<1, 1024>>>(out, B);
}

// round 6
// speedup vs baseline: 1.8435x; 1.8435x over previous
#include <cuda_runtime.h>
#include <math.h>
#include <stdint.h>

// ---------------------------------------------------------------------------
// FedTGPClientLoss:
//   ce    = mean_b [ logsumexp(logits[b,:]) - logits[b, label_b] ]   (0 if !finite)
//   proto = mean_b mean_d (features[b,d] - protos[label_b, d])^2
//   total = ce + proto                                               (ce if !finite)
// Output: [total, ce, proto]  (3 x f32)
//
// Layout: one WARP per row. Register-resident two-pass logsumexp (8 float4
// per lane for C<=1024), warp-shuffle reductions only. Label dtype (int32 vs
// int64) detected per-warp from the first 256B of the labels buffer.
// ---------------------------------------------------------------------------

#define MAXB 32768
__device__ __align__(16) float g_ce[MAXB];
__device__ __align__(16) float g_mse[MAXB];

#define NEG_INF (-__int_as_float(0x7f800000))

__global__ __launch_bounds__(256) void row_kernel(
    const float* __restrict__ logits,
    const int*   __restrict__ l32,     // labels viewed as int32 words
    const float* __restrict__ features,
    const float* __restrict__ protos,
    int B, int C, int D)
{
    const int lane = threadIdx.x & 31;
    const int wid  = threadIdx.x >> 5;
    const int row  = blockIdx.x * 8 + wid;
    if (row >= B) return;

    // ---- per-warp label dtype detection (first 64 int32 words = 256B) ----
    // int64 labels < C  =>  all odd (high) words are 0.
    // int32 labels uniform [0,C)  =>  P(32 odd words all zero) ~ C^-32 ~ 0.
    int probe = l32[2 * lane + 1];
    bool lbl64 = (__ballot_sync(0xFFFFFFFFu, probe != 0) == 0u);

    const int label = lbl64 ? l32[2 * row] : l32[row];

    const float* lr = logits + (size_t)row * C;
    const float lbl_logit = __ldg(lr + label);   // warp-uniform broadcast load

    const float4* lrow = (const float4*)lr;
    const int C4 = C >> 2;
    const int Ctail = C & 3;

    float m = NEG_INF;
    float s = 0.0f;

    if (C4 <= 256) {
        // ---- fast path: logits row register-resident (<=32 floats/lane) ----
        float4 v[8];
        #pragma unroll
        for (int j = 0; j < 8; j++) {
            int idx = j * 32 + lane;
            if (idx < C4) v[j] = lrow[idx];
            else          v[j] = make_float4(NEG_INF, NEG_INF, NEG_INF, NEG_INF);
            m = fmaxf(m, fmaxf(fmaxf(v[j].x, v[j].y), fmaxf(v[j].z, v[j].w)));
        }
        float tval = NEG_INF;
        if (lane < Ctail) { tval = lr[C4 * 4 + lane]; m = fmaxf(m, tval); }

        #pragma unroll
        for (int off = 16; off > 0; off >>= 1)
            m = fmaxf(m, __shfl_xor_sync(0xFFFFFFFFu, m, off));

        #pragma unroll
        for (int j = 0; j < 8; j++) {
            s += __expf(v[j].x - m) + __expf(v[j].y - m)
               + __expf(v[j].z - m) + __expf(v[j].w - m);   // exp(-inf)=0 pads
        }
        if (lane < Ctail) s += __expf(tval - m);
    } else {
        // ---- generic fallback: two passes, second reloads (L1-hot) ----
        for (int idx = lane; idx < C4; idx += 32) {
            float4 q = lrow[idx];
            m = fmaxf(m, fmaxf(fmaxf(q.x, q.y), fmaxf(q.z, q.w)));
        }
        if (lane < Ctail) m = fmaxf(m, lr[C4 * 4 + lane]);
        #pragma unroll
        for (int off = 16; off > 0; off >>= 1)
            m = fmaxf(m, __shfl_xor_sync(0xFFFFFFFFu, m, off));
        for (int idx = lane; idx < C4; idx += 32) {
            float4 q = lrow[idx];
            s += __expf(q.x - m) + __expf(q.y - m)
               + __expf(q.z - m) + __expf(q.w - m);
        }
        if (lane < Ctail) s += __expf(lr[C4 * 4 + lane] - m);
    }

    // ---- per-row proto MSE ----
    const float4* frow = (const float4*)(features + (size_t)row   * D);
    const float4* prow = (const float4*)(protos   + (size_t)label * D);
    const int D4 = D >> 2;
    float sq = 0.0f;
    #pragma unroll 4
    for (int idx = lane; idx < D4; idx += 32) {
        float4 f = frow[idx];
        float4 p = prow[idx];
        float dx = f.x - p.x, dy = f.y - p.y, dz = f.z - p.z, dw = f.w - p.w;
        sq = fmaf(dx, dx, fmaf(dy, dy, fmaf(dz, dz, fmaf(dw, dw, sq))));
    }
    {
        const int Dtail = D & 3;
        if (lane < Dtail) {
            float d = features[(size_t)row * D + D4 * 4 + lane]
                    - protos[(size_t)label * D + D4 * 4 + lane];
            sq = fmaf(d, d, sq);
        }
    }

    // ---- warp reductions (sum) ----
    #pragma unroll
    for (int off = 16; off > 0; off >>= 1) {
        s  += __shfl_xor_sync(0xFFFFFFFFu, s,  off);
        sq += __shfl_xor_sync(0xFFFFFFFFu, sq, off);
    }

    if (lane == 0) {
        float lse = m + __logf(s);
        g_ce[row]  = lse - lbl_logit;
        g_mse[row] = sq / (float)D;
    }
}

// Single-block final reduction in double precision; writes the 3 outputs.
__global__ __launch_bounds__(1024) void final_kernel(float* __restrict__ out, int B) {
    __shared__ double sm[1024];
    const int tid = threadIdx.x;
    const int B4 = B >> 2;
    const float4* ce4 = (const float4*)g_ce;
    const float4* ms4 = (const float4*)g_mse;

    double ce = 0.0, ms = 0.0;
    for (int i = tid; i < B4; i += blockDim.x) {
        float4 a = ce4[i];
        float4 b = ms4[i];
        ce += (double)a.x + (double)a.y + (double)a.z + (double)a.w;
        ms += (double)b.x + (double)b.y + (double)b.z + (double)b.w;
    }
    for (int i = B4 * 4 + tid; i < B; i += blockDim.x) {
        ce += (double)g_ce[i];
        ms += (double)g_mse[i];
    }

    sm[tid] = ce; __syncthreads();
    for (int off = blockDim.x >> 1; off > 0; off >>= 1) {
        if (tid < off) sm[tid] += sm[tid + off];
        __syncthreads();
    }
    double ce_sum = sm[0];
    __syncthreads();
    sm[tid] = ms; __syncthreads();
    for (int off = blockDim.x >> 1; off > 0; off >>= 1) {
        if (tid < off) sm[tid] += sm[tid + off];
        __syncthreads();
    }
    if (tid == 0) {
        float ce_loss = (float)(ce_sum / (double)B);
        if (!isfinite(ce_loss)) ce_loss = 0.0f;
        float proto_loss = (float)(sm[0] / (double)B);
        float total = ce_loss + proto_loss;
        if (!isfinite(total)) total = ce_loss;
        out[0] = total;
        out[1] = ce_loss;
        out[2] = proto_loss;
    }
}

extern "C" void kernel_launch(void* const* d_in, const int* in_sizes, int n_in,
                              void* d_out, int out_size) {
    const float* logits   = (const float*)d_in[0];
    const int*   labels   = (const int*)d_in[1];
    const float* features = (const float*)d_in[2];
    const float* protos   = (const float*)d_in[3];
    float* out = (float*)d_out;

    const int B = in_sizes[1];                 // 16384
    const int C = in_sizes[0] / B;             // 1000
    const int D = in_sizes[2] / B;             // 512

    const int blocks = (B + 7) / 8;            // one warp per row, 8 warps/block
    row_kernel<<<blocks, 256>>>(logits, labels, features, protos, B, C, D);
    final_kernel<<<1, 1024>>>(out, B);
}

// round 7
// speedup vs baseline: 3.3648x; 1.8253x over previous
#include <cuda_runtime.h>
#include <math.h>
#include <stdint.h>

// ---------------------------------------------------------------------------
// FedTGPClientLoss:
//   ce    = mean_b [ logsumexp(logits[b,:]) - logits[b, label_b] ]   (0 if !finite)
//   proto = mean_b mean_d (features[b,d] - protos[label_b, d])^2
//   total = ce + proto                                               (ce if !finite)
// Output: [total, ce, proto]  (3 x f32)
//
// One WARP per row, register-resident two-pass logsumexp, warp-shuffle
// reductions. Final reduction fused via the threadfence-reduction pattern:
// per-block double partials -> last-arriving block reduces L2-hot partials
// and writes the outputs. Single kernel launch.
// ---------------------------------------------------------------------------

#define MAXBLK 8192
__device__ double   g_pce[MAXBLK];
__device__ double   g_pms[MAXBLK];
__device__ unsigned g_count = 0;   // reset by the last block each call

#define NEG_INF (-__int_as_float(0x7f800000))

__global__ __launch_bounds__(256) void row_kernel(
    const float* __restrict__ logits,
    const int*   __restrict__ l32,     // labels viewed as int32 words
    const float* __restrict__ features,
    const float* __restrict__ protos,
    float* __restrict__ out,
    int B, int C, int D)
{
    const int lane = threadIdx.x & 31;
    const int wid  = threadIdx.x >> 5;
    const int row  = blockIdx.x * 8 + wid;
    const bool active = (row < B);

    float ce_f = 0.0f, ms_f = 0.0f;   // lane0-of-warp results

    if (active) {
        // ---- per-warp label dtype detection (first 64 int32 words = 256B) ----
        // int64 labels < C  =>  all odd (high) words are 0.
        // int32 labels uniform [0,C)  =>  P(32 odd words all zero) ~ C^-32 ~ 0.
        int probe = l32[2 * lane + 1];
        bool lbl64 = (__ballot_sync(0xFFFFFFFFu, probe != 0) == 0u);
        const int label = lbl64 ? l32[2 * row] : l32[row];

        const float* lr = logits + (size_t)row * C;
        const float lbl_logit = __ldg(lr + label);   // warp-uniform broadcast

        const float4* lrow = (const float4*)lr;
        const int C4 = C >> 2;
        const int Ctail = C & 3;

        float m = NEG_INF;
        float s = 0.0f;

        if (C4 <= 256) {
            // fast path: row register-resident (<=32 floats/lane)
            float4 v[8];
            #pragma unroll
            for (int j = 0; j < 8; j++) {
                int idx = j * 32 + lane;
                if (idx < C4) v[j] = lrow[idx];
                else          v[j] = make_float4(NEG_INF, NEG_INF, NEG_INF, NEG_INF);
                m = fmaxf(m, fmaxf(fmaxf(v[j].x, v[j].y), fmaxf(v[j].z, v[j].w)));
            }
            float tval = NEG_INF;
            if (lane < Ctail) { tval = lr[C4 * 4 + lane]; m = fmaxf(m, tval); }

            #pragma unroll
            for (int off = 16; off > 0; off >>= 1)
                m = fmaxf(m, __shfl_xor_sync(0xFFFFFFFFu, m, off));

            #pragma unroll
            for (int j = 0; j < 8; j++) {
                s += __expf(v[j].x - m) + __expf(v[j].y - m)
                   + __expf(v[j].z - m) + __expf(v[j].w - m);  // exp(-inf)=0 pads
            }
            if (lane < Ctail) s += __expf(tval - m);
        } else {
            // generic fallback: two passes (second reload is L1-hot)
            for (int idx = lane; idx < C4; idx += 32) {
                float4 q = lrow[idx];
                m = fmaxf(m, fmaxf(fmaxf(q.x, q.y), fmaxf(q.z, q.w)));
            }
            if (lane < Ctail) m = fmaxf(m, lr[C4 * 4 + lane]);
            #pragma unroll
            for (int off = 16; off > 0; off >>= 1)
                m = fmaxf(m, __shfl_xor_sync(0xFFFFFFFFu, m, off));
            for (int idx = lane; idx < C4; idx += 32) {
                float4 q = lrow[idx];
                s += __expf(q.x - m) + __expf(q.y - m)
                   + __expf(q.z - m) + __expf(q.w - m);
            }
            if (lane < Ctail) s += __expf(lr[C4 * 4 + lane] - m);
        }

        // ---- per-row proto MSE ----
        const float4* frow = (const float4*)(features + (size_t)row   * D);
        const float4* prow = (const float4*)(protos   + (size_t)label * D);
        const int D4 = D >> 2;
        float sq = 0.0f;
        #pragma unroll 4
        for (int idx = lane; idx < D4; idx += 32) {
            float4 f = frow[idx];
            float4 p = prow[idx];
            float dx = f.x - p.x, dy = f.y - p.y, dz = f.z - p.z, dw = f.w - p.w;
            sq = fmaf(dx, dx, fmaf(dy, dy, fmaf(dz, dz, fmaf(dw, dw, sq))));
        }
        {
            const int Dtail = D & 3;
            if (lane < Dtail) {
                float d = features[(size_t)row * D + D4 * 4 + lane]
                        - protos[(size_t)label * D + D4 * 4 + lane];
                sq = fmaf(d, d, sq);
            }
        }

        // ---- warp sum reductions ----
        #pragma unroll
        for (int off = 16; off > 0; off >>= 1) {
            s  += __shfl_xor_sync(0xFFFFFFFFu, s,  off);
            sq += __shfl_xor_sync(0xFFFFFFFFu, sq, off);
        }

        ce_f = (m + __logf(s)) - lbl_logit;
        ms_f = sq / (float)D;
    }

    // ---- block reduction of the 8 warp results (doubles) ----
    __shared__ double sm_ce[8], sm_ms[8];
    __shared__ bool   s_is_last;
    if (lane == 0) { sm_ce[wid] = (double)ce_f; sm_ms[wid] = (double)ms_f; }
    __syncthreads();

    if (threadIdx.x == 0) {
        double bce = 0.0, bms = 0.0;
        #pragma unroll
        for (int j = 0; j < 8; j++) { bce += sm_ce[j]; bms += sm_ms[j]; }
        g_pce[blockIdx.x] = bce;
        g_pms[blockIdx.x] = bms;
        __threadfence();
        unsigned prev = atomicAdd(&g_count, 1u);
        s_is_last = (prev == gridDim.x - 1);
    }
    __syncthreads();

    // ---- last-arriving block: reduce L2-hot partials, emit outputs ----
    if (s_is_last) {
        const int tid = threadIdx.x;
        const int nb  = gridDim.x;
        double ce = 0.0, ms = 0.0;
        for (int i = tid; i < nb; i += 256) { ce += g_pce[i]; ms += g_pms[i]; }

        __shared__ double red[512];
        red[tid] = ce; red[256 + tid] = ms;
        __syncthreads();
        #pragma unroll
        for (int off = 128; off > 0; off >>= 1) {
            if (tid < off) {
                red[tid]       += red[tid + off];
                red[256 + tid] += red[256 + tid + off];
            }
            __syncthreads();
        }

        if (tid == 0) {
            float ce_loss = (float)(red[0] / (double)B);
            if (!isfinite(ce_loss)) ce_loss = 0.0f;
            float proto_loss = (float)(red[256] / (double)B);
            float total = ce_loss + proto_loss;
            if (!isfinite(total)) total = ce_loss;
            out[0] = total;
            out[1] = ce_loss;
            out[2] = proto_loss;
            g_count = 0;          // reset for next graph replay
        }
    }
}

extern "C" void kernel_launch(void* const* d_in, const int* in_sizes, int n_in,
                              void* d_out, int out_size) {
    const float* logits   = (const float*)d_in[0];
    const int*   labels   = (const int*)d_in[1];
    const float* features = (const float*)d_in[2];
    const float* protos   = (const float*)d_in[3];
    float* out = (float*)d_out;

    const int B = in_sizes[1];                 // 16384
    const int C = in_sizes[0] / B;             // 1000
    const int D = in_sizes[2] / B;             // 512

    const int blocks = (B + 7) / 8;            // one warp per row, 8 warps/block
    row_kernel<<<blocks, 256>>>(logits, labels, features, protos, out, B, C, D);
}